// round 16
// baseline (speedup 1.0000x reference)
#include <cuda_runtime.h>
#include <cstdint>

#define BB 4
#define NN 2048
#define FIN 128
#define HH 4
#define DKK 32
#define LOG2E 1.4426950408889634f

// Scratch (no cudaMalloc allowed)
__device__ float g_hB[BB*HH*16*16*4*64];   // tf32 H^T, MMA-B fragment order
__device__ float2 g_elx[BB*HH*NN];         // {exp2(el'), exp2(0.2 el')}
__device__ float2 g_erx[BB*HH*NN];         // {exp2(er'), exp2(0.2 er')}
__device__ unsigned g_bits[BB*64*NN];      // ballot-direct bitmask
__device__ float g_pacc[2*16*NN*DKK];      // j-split partial acc
__device__ float g_psum[2*16*NN];          // j-split partial row sums

__device__ __forceinline__ float ex2(float x) {
    float r;
    asm("ex2.approx.f32 %0, %1;" : "=f"(r) : "f"(x));
    return r;
}

// ---------------------------------------------------------------------------
// Kernel A: pack adj -> ballot-direct bitmask. Dual-row iterations (rows r
// and r+16 in flight together) for 2x MLP.
// ---------------------------------------------------------------------------
__global__ __launch_bounds__(256) void pack_adj_k(const int* __restrict__ adj) {
    int t = threadIdx.x, w = t >> 5, lane = t & 31;
    int task = blockIdx.x * 8 + w;
    int ic = task & 63;
    int g  = (task >> 6) & 15;
    int b  = task >> 10;
    int i0 = ic * 32;
    const int4* src = (const int4*)(adj + ((long long)(b * NN + i0)) * NN + g * 128) + lane;
    unsigned m0 = 0, m1 = 0, m2 = 0, m3 = 0;
#pragma unroll 8
    for (int r = 0; r < 16; r++) {
        int4 va = src[(long long)r * (NN / 4)];
        int4 vb = src[(long long)(r + 16) * (NN / 4)];
        unsigned a0 = __ballot_sync(0xffffffffu, va.x != 0);
        unsigned a1 = __ballot_sync(0xffffffffu, va.y != 0);
        unsigned a2 = __ballot_sync(0xffffffffu, va.z != 0);
        unsigned a3 = __ballot_sync(0xffffffffu, va.w != 0);
        unsigned b0 = __ballot_sync(0xffffffffu, vb.x != 0);
        unsigned b1 = __ballot_sync(0xffffffffu, vb.y != 0);
        unsigned b2 = __ballot_sync(0xffffffffu, vb.z != 0);
        unsigned b3 = __ballot_sync(0xffffffffu, vb.w != 0);
        if (lane == r)      { m0 = a0; m1 = a1; m2 = a2; m3 = a3; }
        if (lane == r + 16) { m0 = b0; m1 = b1; m2 = b2; m3 = b3; }
    }
    unsigned* dst = g_bits + ((long long)(b * 16 + g) * 4) * NN + i0 + lane;
    dst[0]      = m0;
    dst[NN]     = m1;
    dst[2 * NN] = m2;
    dst[3 * NN] = m3;
}

// ---------------------------------------------------------------------------
// Kernel B: h = x @ W. 16 rows/block (512 blocks for latency hiding).
// Fragment-ordered tf32 g_hB + fused el/er exp2 pairs.
// ---------------------------------------------------------------------------
__global__ __launch_bounds__(256) void compute_h_k(const float* __restrict__ x,
                                                   const float* __restrict__ W,
                                                   const float* __restrict__ a) {
    __shared__ float xs[16][FIN];
    __shared__ float sT[128][17];
    int t = threadIdx.x, lane = t & 31;
    int row0 = blockIdx.x * 16;
    for (int idx = t; idx < 16 * FIN; idx += 256)
        xs[idx >> 7][idx & 127] = x[(long long)row0 * FIN + idx];
    __syncthreads();

    int c  = t & 127;
    int hh = c >> 5;
    int d  = c & 31;
    int rb = (t >> 7) * 8;

    float acc[8];
#pragma unroll
    for (int r = 0; r < 8; r++) acc[r] = 0.f;

    const float* Wc = W + hh * FIN * DKK + d;
    for (int i0 = 0; i0 < FIN; i0 += 4) {
        float w0 = __ldg(Wc + i0 * DKK);
        float w1 = __ldg(Wc + (i0 + 1) * DKK);
        float w2 = __ldg(Wc + (i0 + 2) * DKK);
        float w3 = __ldg(Wc + (i0 + 3) * DKK);
#pragma unroll
        for (int r = 0; r < 8; r++) {
            float4 xv = *(const float4*)&xs[rb + r][i0];
            acc[r] = fmaf(xv.x, w0, acc[r]);
            acc[r] = fmaf(xv.y, w1, acc[r]);
            acc[r] = fmaf(xv.z, w2, acc[r]);
            acc[r] = fmaf(xv.w, w3, acc[r]);
        }
    }

    int b  = row0 / NN;
    int n0 = row0 % NN;
    int bh = b * HH + hh;

    float al = __ldg(a + hh * 2 * DKK + lane);
    float ar = __ldg(a + hh * 2 * DKK + DKK + lane);
#pragma unroll
    for (int r = 0; r < 8; r++) {
        float el = acc[r] * al, er = acc[r] * ar;
#pragma unroll
        for (int o = 16; o > 0; o >>= 1) {
            el += __shfl_xor_sync(0xffffffffu, el, o);
            er += __shfl_xor_sync(0xffffffffu, er, o);
        }
        if (lane == 0) {
            float elp = el * LOG2E, erp = er * LOG2E;
            g_elx[(long long)bh * NN + n0 + rb + r] =
                make_float2(ex2(elp), ex2(0.2f * elp));
            g_erx[(long long)bh * NN + n0 + rb + r] =
                make_float2(ex2(erp), ex2(0.2f * erp));
        }
    }

#pragma unroll
    for (int r = 0; r < 8; r++) {
        unsigned tv;
        asm("cvt.rna.tf32.f32 %0, %1;" : "=r"(tv) : "f"(acc[r]));
        sT[c][rb + r] = __uint_as_float(tv);
    }
    __syncthreads();

    // g_hB fragment order (interleaved j within each 8); 16 rows = 2 kc.
    int jt  = n0 >> 7;
    int kc0 = (n0 >> 3) & 15;
#pragma unroll
    for (int k = 0; k < 2; k++) {
        int q = t + k * 256;
        int j4    = q & 1;
        int d_loc = (q >> 1) & 7;
        int nt    = (q >> 4) & 3;
        int kcl   = (q >> 6) & 1;
        int h2    = q >> 7;
        int dd   = nt * 8 + d_loc;
        int base = kcl * 8;
        int row  = h2 * 32 + dd;
        float4 v = make_float4(sT[row][base + 2 * j4],
                               sT[row][base + 2 * j4 + 4],
                               sT[row][base + 2 * j4 + 1],
                               sT[row][base + 2 * j4 + 5]);
        long long off = ((((long long)((b * HH + h2) * 16 + jt) * 16 + (kc0 + kcl)) * 4 + nt) * 64)
                        + d_loc * 8 + j4 * 4;
        *(float4*)(g_hB + off) = v;
    }
}

// ---------------------------------------------------------------------------
// Kernel C: masked-softmax + aggregate, j-split S=2, no transcendentals.
// er staged as [c0][mtl][kc] float4 -> ONE broadcast LDS.128 per kc.
// P via packed mul.rn.f32x2 + fmax. Warp = 16 i x 1024 j.
// ---------------------------------------------------------------------------
__device__ __forceinline__ float pmax2(unsigned long long a, unsigned long long b) {
    unsigned long long m;
    asm("mul.rn.f32x2 %0, %1, %2;" : "=l"(m) : "l"(a), "l"(b));
    float lo = __uint_as_float((unsigned)m);
    float hi = __uint_as_float((unsigned)(m >> 32));
    return fmaxf(lo, hi);
}

#define MMA4(accp, A0, A1, A2, A3, B0, B1)                                    \
    asm("mma.sync.aligned.m16n8k8.row.col.f32.tf32.tf32.f32 "                 \
        "{%0,%1,%2,%3}, {%4,%5,%6,%7}, {%8,%9}, {%0,%1,%2,%3};"               \
        : "+f"((accp)[0]), "+f"((accp)[1]), "+f"((accp)[2]), "+f"((accp)[3])  \
        : "r"(A0), "r"(A1), "r"(A2), "r"(A3), "r"(B0), "r"(B1))

__global__ __launch_bounds__(128) void gat_attn_mma_k() {
    __shared__ float4 er4[512];    // 8 KB: [c0][mtl][kc] = {e0.x,e0.y,e4.x,e4.y}
    __shared__ float Bf[4096];     // 16 KB: one 128-j fragment tile

    int t = threadIdx.x, w = t >> 5, lane = t & 31;
    int bid = blockIdx.x;
    int s  = bid & 1;
    int it = (bid >> 1) & 31;
    int hh = (bid >> 6) & 3;
    int b  = bid >> 8;
    int bh = b * HH + hh;

    int iw = it * 64 + w * 16;
    int r  = lane >> 2;
    int c0 = lane & 3;

    // stage er in custom order
    for (int e = t; e < 512; e += 128) {
        int c0e = e >> 7, mtle = (e >> 4) & 7, kce = e & 15;
        int j0 = s * 1024 + mtle * 128 + kce * 8 + c0e;
        float2 u = g_erx[(long long)bh * NN + j0];
        float2 v = g_erx[(long long)bh * NN + j0 + 4];
        er4[e] = make_float4(u.x, u.y, v.x, v.y);
    }
    float2 El0 = g_elx[(long long)bh * NN + iw + r];
    float2 El1 = g_elx[(long long)bh * NN + iw + r + 8];
    unsigned long long El0p, El1p;
    asm("mov.b64 %0, {%1,%2};" : "=l"(El0p) : "f"(El0.x), "f"(El0.y));
    asm("mov.b64 %0, {%1,%2};" : "=l"(El1p) : "f"(El1.x), "f"(El1.y));

    float acc[4][4];
    float accS[4];
#pragma unroll
    for (int nt = 0; nt < 4; nt++)
#pragma unroll
        for (int q = 0; q < 4; q++) acc[nt][q] = 0.f;
#pragma unroll
    for (int q = 0; q < 4; q++) accS[q] = 0.f;

    const float* hBb = g_hB + (long long)bh * 65536;
    const unsigned* bitb = g_bits + (long long)b * 64 * NN;
    const unsigned ONE = 0x3F800000u;

    for (int mtl = 0; mtl < 8; mtl++) {
        int g = s * 8 + mtl;
        __syncthreads();
        {
            const float4* src = (const float4*)(hBb + g * 4096);
            float4* dst = (float4*)Bf;
#pragma unroll
            for (int k = 0; k < 8; k++) dst[t + k * 128] = src[t + k * 128];
        }
        const unsigned* bw = bitb + (long long)(g * 4 + c0) * NN + iw + r;
        unsigned w0a = bw[0], w0b = bw[8];
        __syncthreads();

        const float4* erp = er4 + c0 * 128 + mtl * 16;
#pragma unroll
        for (int kc = 0; kc < 16; kc++) {
            float4 e = erp[kc];
            unsigned long long e03, e47;
            asm("mov.b64 %0, {%1,%2};" : "=l"(e03) : "f"(e.x), "f"(e.y));
            asm("mov.b64 %0, {%1,%2};" : "=l"(e47) : "f"(e.z), "f"(e.w));

            float p00 = pmax2(El0p, e03);
            float p01 = pmax2(El1p, e03);
            float p02 = pmax2(El0p, e47);
            float p03 = pmax2(El1p, e47);

            unsigned bm0 = 1u << (2 * kc);
            unsigned bm1 = 1u << (2 * kc + 1);
            unsigned a0 = (w0a & bm0) ? __float_as_uint(p00) : 0u;
            unsigned a1 = (w0b & bm0) ? __float_as_uint(p01) : 0u;
            unsigned a2 = (w0a & bm1) ? __float_as_uint(p02) : 0u;
            unsigned a3 = (w0b & bm1) ? __float_as_uint(p03) : 0u;

            const float2* bp = (const float2*)(Bf + kc * 256) + lane;
#pragma unroll
            for (int nt = 0; nt < 4; nt++) {
                float2 bv = bp[nt * 32];
                MMA4(acc[nt], a0, a1, a2, a3,
                     __float_as_uint(bv.x), __float_as_uint(bv.y));
            }
            MMA4(accS, a0, a1, a2, a3, ONE, ONE);   // row sums
        }
    }

    // ---- write unnormalized partials ----
    int sb = s * 16 + bh;
    int gi = iw + r;
    if (c0 == 0) {
        g_psum[(long long)sb * NN + gi]     = accS[0];
        g_psum[(long long)sb * NN + gi + 8] = accS[2];
    }
    float* pb = g_pacc + ((long long)sb * NN + gi) * DKK;
#pragma unroll
    for (int nt = 0; nt < 4; nt++) {
        int col = nt * 8 + 2 * c0;
        *(float2*)(pb + col)           = make_float2(acc[nt][0], acc[nt][1]);
        *(float2*)(pb + 8 * DKK + col) = make_float2(acc[nt][2], acc[nt][3]);
    }
}

// ---------------------------------------------------------------------------
// Kernel D: reduce the 2 j-split partials + normalize + write out.
// ---------------------------------------------------------------------------
__global__ __launch_bounds__(256) void reduce_k(float* __restrict__ out) {
    int q = blockIdx.x * 256 + threadIdx.x;   // 262144 threads
    int row  = q >> 3;
    int dseg = (q & 7) * 4;
    int bh = row >> 11;
    int i  = row & 2047;
    float s0 = g_psum[(long long)bh * NN + i];
    float s1 = g_psum[(long long)(16 + bh) * NN + i];
    float4 u = *(const float4*)(g_pacc + ((long long)bh * NN + i) * DKK + dseg);
    float4 v = *(const float4*)(g_pacc + ((long long)(16 + bh) * NN + i) * DKK + dseg);
    float inv = 1.f / (s0 + s1);
    *(float4*)(out + ((long long)bh * NN + i) * DKK + dseg) =
        make_float4((u.x + v.x) * inv, (u.y + v.y) * inv,
                    (u.z + v.z) * inv, (u.w + v.w) * inv);
}

// ---------------------------------------------------------------------------
extern "C" void kernel_launch(void* const* d_in, const int* in_sizes, int n_in,
                              void* d_out, int out_size) {
    const float* x   = (const float*)d_in[0];
    const int*   adj = (const int*)d_in[1];
    const float* W   = (const float*)d_in[2];
    const float* a   = (const float*)d_in[3];
    float* out = (float*)d_out;

    pack_adj_k<<<512, 256>>>(adj);
    compute_h_k<<<(BB * NN) / 16, 256>>>(x, W, a);
    gat_attn_mma_k<<<BB * HH * 32 * 2, 128>>>();
    reduce_k<<<1024, 256>>>(out);
}